// round 15
// baseline (speedup 1.0000x reference)
#include <cuda_runtime.h>
#include <cstdint>

// Encoding: B=64, C=512, N=784, K=32. x:(B,C,N) f32; out:(B,K,C) f32.
// K1: logits mma tf32 + softmax -> A ([b][n][k]) + wsum.
//     float4 staging, no prefetch buffer, 2 CTAs/SM for cross-CTA latency hiding.
// K2 (round-10 proven): out = A^T x, 64-c blocks, double-buffered, fused epilogue.

#define CDIM 512
#define KD 32
#define NPIX 784
#define BDIM 64
#define CH1 9
#define TS 16
#define TILES1 49

__device__ float g_A[(size_t)BDIM * NPIX * KD];     // 6.4 MB, [b][n][k]
__device__ float g_wsum[BDIM * CH1 * KD];

__device__ __forceinline__ float rtf32(float v) {
    asm("cvt.rna.tf32.f32 %0, %1;" : "=f"(v) : "f"(v));
    return v;
}
__device__ __forceinline__ void mma8(float* d, uint32_t a0, uint32_t a1,
                                     uint32_t a2, uint32_t a3,
                                     uint32_t b0, uint32_t b1) {
    asm volatile(
        "mma.sync.aligned.m16n8k8.row.col.f32.tf32.tf32.f32 "
        "{%0,%1,%2,%3}, {%4,%5,%6,%7}, {%8,%9}, {%0,%1,%2,%3};"
        : "+f"(d[0]), "+f"(d[1]), "+f"(d[2]), "+f"(d[3])
        : "r"(a0), "r"(a1), "r"(a2), "r"(a3), "r"(b0), "r"(b1));
}
#define BITS(f) __float_as_uint(f)

// =========================== K1: logits + softmax ===========================
__global__ __launch_bounds__(256, 2) void enc_k1(const float* __restrict__ x,
                                                 const float* __restrict__ cw,
                                                 const float* __restrict__ scale) {
    const int b = blockIdx.x / CH1, ch = blockIdx.x % CH1;
    const int tile0 = ch * TILES1 / CH1, tile1 = (ch + 1) * TILES1 / CH1;
    const int t = threadIdx.x, w = t >> 5, l = t & 31;
    const int kt = w & 3, h = w >> 2;         // warp = (k-tile, c-half)

    __shared__ float x_s[TS * 516];
    __shared__ float xc_s[TS * 34];
    __shared__ float red_s[4 * 32 * 4];
    __shared__ float part_s[TS * 68];         // xsq partials, [n][64 c-slots], f4-aligned
    __shared__ float csq_s[KD], scl_s[KD];
    __shared__ float wsum_s[8][KD];

    if (t < KD) scl_s[t] = __ldg(&scale[t]);
#pragma unroll
    for (int kk = 0; kk < 4; kk++) {
        int k = 4 * w + kk;
        float s = 0.f;
#pragma unroll
        for (int q = 0; q < 4; q++) {
            float4 v = __ldg((const float4*)&cw[k * CDIM + l * 16 + 4 * q]);
            float e0 = rtf32(v.x), e1 = rtf32(v.y), e2 = rtf32(v.z), e3 = rtf32(v.w);
            s += e0 * e0 + e1 * e1 + e2 * e2 + e3 * e3;
        }
#pragma unroll
        for (int o = 16; o; o >>= 1) s += __shfl_xor_sync(~0u, s, o);
        if (l == 0) csq_s[k] = s;
    }

    // persistent codeword B-fragments (tf32): warp covers k=8kt..+7, c-half h
    uint32_t cwf0[32], cwf1[32];
    const int crow = kt * 8 + (l >> 2), cp = l & 3;
#pragma unroll
    for (int s = 0; s < 32; s++) {
        int c = h * 256 + 8 * s + cp;
        cwf0[s] = BITS(rtf32(__ldg(&cw[crow * CDIM + c])));
        cwf1[s] = BITS(rtf32(__ldg(&cw[crow * CDIM + c + 4])));
    }

    float wsum_acc = 0.f;
    const float* xb = x + (size_t)b * CDIM * NPIX;
    const int nq = t & 3, cs = t >> 2;        // staging: n-quad, c-row (0..63)

    for (int tile = tile0; tile < tile1; tile++) {
        const int n0 = tile * TS;
        __syncthreads();
        // stage x tile via 8 LDG.128 (4 consecutive n per c-row) + xsq quad partials
        float xsq4[4] = {0.f, 0.f, 0.f, 0.f};
#pragma unroll
        for (int i = 0; i < 8; i++) {
            int c = cs + 64 * i;
            float4 v = __ldg((const float4*)&xb[(size_t)c * NPIX + n0 + 4 * nq]);
            x_s[(4 * nq + 0) * 516 + c] = v.x;
            x_s[(4 * nq + 1) * 516 + c] = v.y;
            x_s[(4 * nq + 2) * 516 + c] = v.z;
            x_s[(4 * nq + 3) * 516 + c] = v.w;
            xsq4[0] = fmaf(v.x, v.x, xsq4[0]);
            xsq4[1] = fmaf(v.y, v.y, xsq4[1]);
            xsq4[2] = fmaf(v.z, v.z, xsq4[2]);
            xsq4[3] = fmaf(v.w, v.w, xsq4[3]);
        }
#pragma unroll
        for (int j = 0; j < 4; j++) part_s[(4 * nq + j) * 68 + cs] = xsq4[j];
        __syncthreads();

        // phase 1: xc = x . cw^T, 32 k-steps, 2 accumulation chains (raw fp32 -> HW tf32)
        float dA[4] = {0.f, 0.f, 0.f, 0.f}, dB[4] = {0.f, 0.f, 0.f, 0.f};
        const int r0 = (l >> 2) * 516, r1 = r0 + 8 * 516;
#pragma unroll
        for (int s = 0; s < 32; s++) {
            int c = h * 256 + 8 * s + cp;
            uint32_t a0 = BITS(x_s[r0 + c]);
            uint32_t a1 = BITS(x_s[r1 + c]);
            uint32_t a2 = BITS(x_s[r0 + c + 4]);
            uint32_t a3 = BITS(x_s[r1 + c + 4]);
            mma8((s & 1) ? dB : dA, a0, a1, a2, a3, cwf0[s], cwf1[s]);
        }
        float d4[4];
#pragma unroll
        for (int i = 0; i < 4; i++) d4[i] = dA[i] + dB[i];
        if (h == 1)
            *(float4*)&red_s[(kt * 32 + l) * 4] = make_float4(d4[0], d4[1], d4[2], d4[3]);
        __syncthreads();
        if (h == 0) {
            float4 rr = *(const float4*)&red_s[(kt * 32 + l) * 4];
            d4[0] += rr.x; d4[1] += rr.y; d4[2] += rr.z; d4[3] += rr.w;
            int rrow = l >> 2, cc = kt * 8 + 2 * (l & 3);
            *(float2*)&xc_s[rrow * 34 + cc] = make_float2(d4[0], d4[1]);
            *(float2*)&xc_s[(rrow + 8) * 34 + cc] = make_float2(d4[2], d4[3]);
        }
        __syncthreads();

        // softmax: warp w rows {w, w+8}, lane = k; xsq via broadcast LDS.128
#pragma unroll
        for (int r = 0; r < 2; r++) {
            int n = w + 8 * r;
            float xs = 0.f;
#pragma unroll
            for (int q = 0; q < 16; q++) {
                float4 p = *(const float4*)&part_s[n * 68 + 4 * q];
                xs += (p.x + p.y) + (p.z + p.w);
            }
            float xc = xc_s[n * 34 + l];
            float dd = scl_s[l] * (xs - 2.f * xc + csq_s[l]);
            float m = dd;
#pragma unroll
            for (int o = 16; o; o >>= 1) m = fmaxf(m, __shfl_xor_sync(~0u, m, o));
            float e = __expf(dd - m);
            float ss = e;
#pragma unroll
            for (int o = 16; o; o >>= 1) ss += __shfl_xor_sync(~0u, ss, o);
            float a = rtf32(__fdividef(e, ss));
            wsum_acc += a;
            g_A[((size_t)b * NPIX + n0 + n) * KD + l] = a;   // coalesced
        }
    }

    wsum_s[w][l] = wsum_acc;
    __syncthreads();
    if (t < KD) {
        float s = 0.f;
#pragma unroll
        for (int ww = 0; ww < 8; ww++) s += wsum_s[ww][t];
        g_wsum[(b * CH1 + ch) * KD + t] = s;
    }
}

// ==== K2: out = A^T x, 64-c blocks, double-buffered, fused epilogue (round-10) ====
// x_s: n-group j (=n/4, 0..7) major, stride 66 float4; (j, c, n%4) at (j*66+c)*4 + n%4.
__global__ __launch_bounds__(256) void enc_k2(const float* __restrict__ x,
                                              const float* __restrict__ cw,
                                              float* __restrict__ out) {
    const int b = blockIdx.x >> 3, cb = blockIdx.x & 7;   // cb: 64-c block
    const int t = threadIdx.x, w = t >> 5, l = t & 31;
    const int mt = w & 1, cq = w >> 1;   // warp = (k-half 16, c-quarter 16)

    __shared__ float A_s[2][32 * 40];      // [32n][32k], stride 40
    __shared__ float x_s[2][8 * 66 * 4];   // blocked, 2112 floats/buf
    __shared__ float wsum_s[KD];

    if (t < KD) {
        float s = 0.f;
#pragma unroll
        for (int ch = 0; ch < CH1; ch++) s += g_wsum[(b * CH1 + ch) * KD + t];
        wsum_s[t] = s;
    }

    float acc[2][4];
#pragma unroll
    for (int i = 0; i < 2; i++)
#pragma unroll
        for (int j = 0; j < 4; j++) acc[i][j] = 0.f;

    const float* xb = x + ((size_t)b * CDIM + cb * 64) * NPIX;
    const float* Ab = g_A + (size_t)b * NPIX * KD;
    const int ar = t >> 3, ak4 = t & 7;   // A staging: n row, k-float4
    const int xc_ = t >> 2, xj = t & 3;   // x staging: c row, n-group (and +4)

#define K2_LDG(n0, av, v0, v1) do { \
        av = ((n0) + ar < NPIX) \
            ? __ldg((const float4*)&Ab[(size_t)((n0) + ar) * KD + 4 * ak4]) \
            : make_float4(0.f, 0.f, 0.f, 0.f); \
        v0 = ((n0) + 4 * xj < NPIX) \
            ? __ldg((const float4*)&xb[(size_t)xc_ * NPIX + (n0) + 4 * xj]) \
            : make_float4(0.f, 0.f, 0.f, 0.f); \
        v1 = ((n0) + 4 * (xj + 4) < NPIX) \
            ? __ldg((const float4*)&xb[(size_t)xc_ * NPIX + (n0) + 4 * (xj + 4)]) \
            : make_float4(0.f, 0.f, 0.f, 0.f); \
    } while (0)

#define K2_STS(bi, av, v0, v1) do { \
        *(float4*)&A_s[bi][ar * 40 + 4 * ak4] = av; \
        *(float4*)&x_s[bi][(xj * 66 + xc_) * 4] = v0; \
        *(float4*)&x_s[bi][((xj + 4) * 66 + xc_) * 4] = v1; \
    } while (0)

    {   // prologue: stage tile 0 into buffer 0
        float4 av, v0, v1;
        K2_LDG(0, av, v0, v1);
        K2_STS(0, av, v0, v1);
    }
    __syncthreads();

    const int q3 = l & 3, c7 = l >> 2;

    for (int tl = 0; tl < 25; tl++) {
        const int cur = tl & 1;
        float4 av, v0, v1;
        if (tl < 24) { K2_LDG((tl + 1) * 32, av, v0, v1); }   // overlap with mma

#pragma unroll
        for (int ks = 0; ks < 4; ks++) {
            int pn = 8 * ks + q3;
            uint32_t a0 = BITS(A_s[cur][pn * 40 + mt * 16 + c7]);
            uint32_t a1 = BITS(A_s[cur][pn * 40 + mt * 16 + c7 + 8]);
            uint32_t a2 = BITS(A_s[cur][(pn + 4) * 40 + mt * 16 + c7]);
            uint32_t a3 = BITS(A_s[cur][(pn + 4) * 40 + mt * 16 + c7 + 8]);
#pragma unroll
            for (int nt = 0; nt < 2; nt++) {
                int crow = cq * 16 + nt * 8 + c7;
                uint32_t b0 = BITS(x_s[cur][((2 * ks) * 66 + crow) * 4 + q3]);
                uint32_t b1 = BITS(x_s[cur][((2 * ks + 1) * 66 + crow) * 4 + q3]);
                mma8(acc[nt], a0, a1, a2, a3, b0, b1);
            }
        }
        if (tl < 24) { K2_STS(1 - cur, av, v0, v1); }   // write other buffer
        __syncthreads();
    }

    // fused epilogue: out = acc - wsum*cw
    const int k0 = mt * 16 + c7;
#pragma unroll
    for (int nt = 0; nt < 2; nt++) {
        int c = cb * 64 + cq * 16 + nt * 8 + 2 * q3;
#pragma unroll
        for (int half = 0; half < 2; half++) {
            int k = k0 + 8 * half;
            float2 cv = __ldg((const float2*)&cw[k * CDIM + c]);
            float ws = wsum_s[k];
            float2 o;
            o.x = acc[nt][2 * half]     - ws * cv.x;
            o.y = acc[nt][2 * half + 1] - ws * cv.y;
            *(float2*)&out[((size_t)b * KD + k) * CDIM + c] = o;
        }
    }
}

extern "C" void kernel_launch(void* const* d_in, const int* in_sizes, int n_in,
                              void* d_out, int out_size) {
    const float* x     = (const float*)d_in[0];
    const float* cw    = (const float*)d_in[1];
    const float* scale = (const float*)d_in[2];
    enc_k1<<<BDIM * CH1, 256>>>(x, cw, scale);
    enc_k2<<<BDIM * 8, 256>>>(x, cw, (float*)d_out);
}

// round 16
// speedup vs baseline: 1.0659x; 1.0659x over previous
#include <cuda_runtime.h>
#include <cstdint>

// Encoding: B=64, C=512, N=784, K=32. x:(B,C,N) f32; out:(B,K,C) f32.
// Round-10 proven pair + 2 empty dummy kernels so ncu (-s 5 -c 1) captures enc_k1.
// K1: logits mma tf32 + softmax -> A ([b][n][k], tf32) + wsum. Register-prefetched staging.
// K2: out = A^T x, 64-c blocks, double-buffered, blocked conflict-free x_s, fused epilogue.

#define CDIM 512
#define KD 32
#define NPIX 784
#define BDIM 64
#define CH1 9
#define TS 16
#define TILES1 49

__device__ float g_A[(size_t)BDIM * NPIX * KD];     // 6.4 MB, [b][n][k]
__device__ float g_wsum[BDIM * CH1 * KD];

__device__ __forceinline__ float rtf32(float v) {
    asm("cvt.rna.tf32.f32 %0, %1;" : "=f"(v) : "f"(v));
    return v;
}
__device__ __forceinline__ void mma8(float* d, uint32_t a0, uint32_t a1,
                                     uint32_t a2, uint32_t a3,
                                     uint32_t b0, uint32_t b1) {
    asm volatile(
        "mma.sync.aligned.m16n8k8.row.col.f32.tf32.tf32.f32 "
        "{%0,%1,%2,%3}, {%4,%5,%6,%7}, {%8,%9}, {%0,%1,%2,%3};"
        : "+f"(d[0]), "+f"(d[1]), "+f"(d[2]), "+f"(d[3])
        : "r"(a0), "r"(a1), "r"(a2), "r"(a3), "r"(b0), "r"(b1));
}
#define BITS(f) __float_as_uint(f)

// empty marker kernels: shift ncu's launch index so capture lands on enc_k1
__global__ void enc_mark1() {}
__global__ void enc_mark2() {}

// =========================== K1: logits + softmax ===========================
__global__ __launch_bounds__(256) void enc_k1(const float* __restrict__ x,
                                              const float* __restrict__ cw,
                                              const float* __restrict__ scale) {
    const int b = blockIdx.x / CH1, ch = blockIdx.x % CH1;
    const int tile0 = ch * TILES1 / CH1, tile1 = (ch + 1) * TILES1 / CH1;
    const int t = threadIdx.x, w = t >> 5, l = t & 31;
    const int kt = w & 3, h = w >> 2;         // warp = (k-tile, c-half)

    __shared__ float x_s[TS * 516];
    __shared__ float xc_s[TS * 34];
    __shared__ float red_s[4 * 32 * 4];
    __shared__ float part_s[TS * 17];
    __shared__ float csq_s[KD], scl_s[KD];
    __shared__ float wsum_s[8][KD];

    if (t < KD) scl_s[t] = __ldg(&scale[t]);
#pragma unroll
    for (int kk = 0; kk < 4; kk++) {
        int k = 4 * w + kk;
        float s = 0.f;
#pragma unroll
        for (int q = 0; q < 4; q++) {
            float4 v = __ldg((const float4*)&cw[k * CDIM + l * 16 + 4 * q]);
            float e0 = rtf32(v.x), e1 = rtf32(v.y), e2 = rtf32(v.z), e3 = rtf32(v.w);
            s += e0 * e0 + e1 * e1 + e2 * e2 + e3 * e3;
        }
#pragma unroll
        for (int o = 16; o; o >>= 1) s += __shfl_xor_sync(~0u, s, o);
        if (l == 0) csq_s[k] = s;
    }

    // persistent codeword B-fragments (tf32): warp covers k=8kt..+7, c-half h
    uint32_t cwf0[32], cwf1[32];
    const int crow = kt * 8 + (l >> 2), cp = l & 3;
#pragma unroll
    for (int s = 0; s < 32; s++) {
        int c = h * 256 + 8 * s + cp;
        cwf0[s] = BITS(rtf32(__ldg(&cw[crow * CDIM + c])));
        cwf1[s] = BITS(rtf32(__ldg(&cw[crow * CDIM + c + 4])));
    }

    float wsum_acc = 0.f;
    const float* xb = x + (size_t)b * CDIM * NPIX;
    const int nl = t & 15, cb16 = t >> 4;

    float buf[32];
#define LDREG(n0) _Pragma("unroll") \
    for (int i = 0; i < 32; i++) buf[i] = __ldg(&xb[(cb16 + 16 * i) * NPIX + (n0) + nl]);

    LDREG(tile0 * TS);
    for (int tile = tile0; tile < tile1; tile++) {
        const int n0 = tile * TS;
        __syncthreads();
        // commit prefetched tile (tf32) + xsq partial
        float xsqp = 0.f;
#pragma unroll
        for (int i = 0; i < 32; i++) {
            float v = rtf32(buf[i]);
            x_s[nl * 516 + cb16 + 16 * i] = v;
            xsqp = fmaf(v, v, xsqp);
        }
        part_s[nl * 17 + cb16] = xsqp;
        __syncthreads();
        if (tile + 1 < tile1) { LDREG(n0 + TS); }   // overlap next-tile DRAM latency

        // phase 1: xc = x . cw^T, 32 k-steps, 2 accumulation chains
        float dA[4] = {0.f, 0.f, 0.f, 0.f}, dB[4] = {0.f, 0.f, 0.f, 0.f};
        const int r0 = (l >> 2) * 516, r1 = r0 + 8 * 516;
#pragma unroll
        for (int s = 0; s < 32; s++) {
            int c = h * 256 + 8 * s + cp;
            uint32_t a0 = BITS(x_s[r0 + c]);
            uint32_t a1 = BITS(x_s[r1 + c]);
            uint32_t a2 = BITS(x_s[r0 + c + 4]);
            uint32_t a3 = BITS(x_s[r1 + c + 4]);
            mma8((s & 1) ? dB : dA, a0, a1, a2, a3, cwf0[s], cwf1[s]);
        }
        float d4[4];
#pragma unroll
        for (int i = 0; i < 4; i++) d4[i] = dA[i] + dB[i];
        if (h == 1)
            *(float4*)&red_s[(kt * 32 + l) * 4] = make_float4(d4[0], d4[1], d4[2], d4[3]);
        __syncthreads();
        if (h == 0) {
            float4 rr = *(const float4*)&red_s[(kt * 32 + l) * 4];
            d4[0] += rr.x; d4[1] += rr.y; d4[2] += rr.z; d4[3] += rr.w;
            int rrow = l >> 2, cc = kt * 8 + 2 * (l & 3);
            *(float2*)&xc_s[rrow * 34 + cc] = make_float2(d4[0], d4[1]);
            *(float2*)&xc_s[(rrow + 8) * 34 + cc] = make_float2(d4[2], d4[3]);
        }
        __syncthreads();

        // softmax: warp w rows {w, w+8}, lane = k
#pragma unroll
        for (int r = 0; r < 2; r++) {
            int n = w + 8 * r;
            float xs = 0.f;
#pragma unroll
            for (int q = 0; q < 16; q++) xs += part_s[n * 17 + q];
            float xc = xc_s[n * 34 + l];
            float dd = scl_s[l] * (xs - 2.f * xc + csq_s[l]);
            float m = dd;
#pragma unroll
            for (int o = 16; o; o >>= 1) m = fmaxf(m, __shfl_xor_sync(~0u, m, o));
            float e = __expf(dd - m);
            float ss = e;
#pragma unroll
            for (int o = 16; o; o >>= 1) ss += __shfl_xor_sync(~0u, ss, o);
            float a = rtf32(__fdividef(e, ss));
            wsum_acc += a;
            g_A[((size_t)b * NPIX + n0 + n) * KD + l] = a;   // coalesced
        }
    }

    wsum_s[w][l] = wsum_acc;
    __syncthreads();
    if (t < KD) {
        float s = 0.f;
#pragma unroll
        for (int ww = 0; ww < 8; ww++) s += wsum_s[ww][t];
        g_wsum[(b * CH1 + ch) * KD + t] = s;
    }
}

// ==== K2: out = A^T x, double-buffered, blocked conflict-free x_s, fused epilogue ====
// x_s: n-group j (=n/4, 0..7) major, stride 66 float4; (j, c, n%4) at (j*66+c)*4 + n%4.
__global__ __launch_bounds__(256) void enc_k2(const float* __restrict__ x,
                                              const float* __restrict__ cw,
                                              float* __restrict__ out) {
    const int b = blockIdx.x >> 3, cb = blockIdx.x & 7;   // cb: 64-c block
    const int t = threadIdx.x, w = t >> 5, l = t & 31;
    const int mt = w & 1, cq = w >> 1;   // warp = (k-half 16, c-quarter 16)

    __shared__ float A_s[2][32 * 40];      // [32n][32k], stride 40
    __shared__ float x_s[2][8 * 66 * 4];   // blocked, 2112 floats/buf
    __shared__ float wsum_s[KD];

    if (t < KD) {
        float s = 0.f;
#pragma unroll
        for (int ch = 0; ch < CH1; ch++) s += g_wsum[(b * CH1 + ch) * KD + t];
        wsum_s[t] = s;
    }

    float acc[2][4];
#pragma unroll
    for (int i = 0; i < 2; i++)
#pragma unroll
        for (int j = 0; j < 4; j++) acc[i][j] = 0.f;

    const float* xb = x + ((size_t)b * CDIM + cb * 64) * NPIX;
    const float* Ab = g_A + (size_t)b * NPIX * KD;
    const int ar = t >> 3, ak4 = t & 7;   // A staging: n row, k-float4
    const int xc_ = t >> 2, xj = t & 3;   // x staging: c row, n-group (and +4)

#define K2_LDG(n0, av, v0, v1) do { \
        av = ((n0) + ar < NPIX) \
            ? __ldg((const float4*)&Ab[(size_t)((n0) + ar) * KD + 4 * ak4]) \
            : make_float4(0.f, 0.f, 0.f, 0.f); \
        v0 = ((n0) + 4 * xj < NPIX) \
            ? __ldg((const float4*)&xb[(size_t)xc_ * NPIX + (n0) + 4 * xj]) \
            : make_float4(0.f, 0.f, 0.f, 0.f); \
        v1 = ((n0) + 4 * (xj + 4) < NPIX) \
            ? __ldg((const float4*)&xb[(size_t)xc_ * NPIX + (n0) + 4 * (xj + 4)]) \
            : make_float4(0.f, 0.f, 0.f, 0.f); \
    } while (0)

#define K2_STS(bi, av, v0, v1) do { \
        *(float4*)&A_s[bi][ar * 40 + 4 * ak4] = av; \
        *(float4*)&x_s[bi][(xj * 66 + xc_) * 4] = v0; \
        *(float4*)&x_s[bi][((xj + 4) * 66 + xc_) * 4] = v1; \
    } while (0)

    {   // prologue: stage tile 0 into buffer 0
        float4 av, v0, v1;
        K2_LDG(0, av, v0, v1);
        K2_STS(0, av, v0, v1);
    }
    __syncthreads();

    const int q3 = l & 3, c7 = l >> 2;

    for (int tl = 0; tl < 25; tl++) {
        const int cur = tl & 1;
        float4 av, v0, v1;
        if (tl < 24) { K2_LDG((tl + 1) * 32, av, v0, v1); }   // overlap with mma

#pragma unroll
        for (int ks = 0; ks < 4; ks++) {
            int pn = 8 * ks + q3;
            uint32_t a0 = BITS(A_s[cur][pn * 40 + mt * 16 + c7]);
            uint32_t a1 = BITS(A_s[cur][pn * 40 + mt * 16 + c7 + 8]);
            uint32_t a2 = BITS(A_s[cur][(pn + 4) * 40 + mt * 16 + c7]);
            uint32_t a3 = BITS(A_s[cur][(pn + 4) * 40 + mt * 16 + c7 + 8]);
#pragma unroll
            for (int nt = 0; nt < 2; nt++) {
                int crow = cq * 16 + nt * 8 + c7;
                uint32_t b0 = BITS(x_s[cur][((2 * ks) * 66 + crow) * 4 + q3]);
                uint32_t b1 = BITS(x_s[cur][((2 * ks + 1) * 66 + crow) * 4 + q3]);
                mma8(acc[nt], a0, a1, a2, a3, b0, b1);
            }
        }
        if (tl < 24) { K2_STS(1 - cur, av, v0, v1); }   // write other buffer
        __syncthreads();
    }

    // fused epilogue: out = acc - wsum*cw
    const int k0 = mt * 16 + c7;
#pragma unroll
    for (int nt = 0; nt < 2; nt++) {
        int c = cb * 64 + cq * 16 + nt * 8 + 2 * q3;
#pragma unroll
        for (int half = 0; half < 2; half++) {
            int k = k0 + 8 * half;
            float2 cv = __ldg((const float2*)&cw[k * CDIM + c]);
            float ws = wsum_s[k];
            float2 o;
            o.x = acc[nt][2 * half]     - ws * cv.x;
            o.y = acc[nt][2 * half + 1] - ws * cv.y;
            *(float2*)&out[((size_t)b * KD + k) * CDIM + c] = o;
        }
    }
}

extern "C" void kernel_launch(void* const* d_in, const int* in_sizes, int n_in,
                              void* d_out, int out_size) {
    const float* x     = (const float*)d_in[0];
    const float* cw    = (const float*)d_in[1];
    const float* scale = (const float*)d_in[2];
    // 4 nodes per replay: D, K1, D, K2  -> ncu launch #5 (replay 2, node 1) = enc_k1
    enc_mark1<<<1, 32>>>();
    enc_k1<<<BDIM * CH1, 256>>>(x, cw, scale);
    enc_mark2<<<1, 32>>>();
    enc_k2<<<BDIM * 8, 256>>>(x, cw, (float*)d_out);
}